// round 11
// baseline (speedup 1.0000x reference)
#include <cuda_runtime.h>
#include <cuda_bf16.h>
#include <cstdint>

// Problem constants
#define B_     8192
#define NSITE  256
#define D_     128
#define OUT_   10
#define NSTEP  254
#define BM     32            // samples per CTA
#define NCTA   (B_ / BM)     // 256 CTAs -> 2 per SM on most SMs
#define THREADS 128          // 4 warps, N-split only
#define PREP_T  256

// Dynamic smem layout (bytes): A double-buffer (2 x 16KB) + staging + mbar
#define SM_FL   32768        // float staging area begins here
#define SM_MB   (SM_FL + 2304)
#define SMEM_TOTAL (SM_MB + 16)

// Scratch globals
__device__ float g_cos[NSITE * B_];                      // 8 MB
__device__ float g_sin[NSITE * B_];                      // 8 MB
// Fragment-major pre-split B: per step 8192 uint4 chunks laid out so that
// uint4 index = [step:*][c2:3][w:2][ldg:3][lane:5]
// ldg f-pair: f = mat*8 + parity*4 + n8 (n8 0..3); uint4 = {f_ev k0, f_ev k1,
// f_od k0, f_od k1}
__device__ __nv_bfloat16 g_B[(size_t)NSTEP * 65536];     // 33.3 MB

// ---------------------------------------------------------------------------
// Base-ISA asm helpers
// ---------------------------------------------------------------------------
__device__ __forceinline__ uint32_t smem_u32(const void* p) {
    uint32_t a;
    asm("{ .reg .u64 t; cvta.to.shared.u64 t, %1; cvt.u32.u64 %0, t; }"
        : "=r"(a) : "l"(p));
    return a;
}
__device__ __forceinline__ void ldsm4(uint32_t* r, uint32_t a) {
    asm volatile("ldmatrix.sync.aligned.m8n8.x4.shared.b16 {%0,%1,%2,%3}, [%4];"
                 : "=r"(r[0]), "=r"(r[1]), "=r"(r[2]), "=r"(r[3]) : "r"(a));
}
__device__ __forceinline__ void stsm4(uint32_t a, uint32_t r0, uint32_t r1,
                                      uint32_t r2, uint32_t r3) {
    asm volatile("stmatrix.sync.aligned.m8n8.x4.shared.b16 [%0], {%1,%2,%3,%4};"
                 :: "r"(a), "r"(r0), "r"(r1), "r"(r2), "r"(r3) : "memory");
}
__device__ __forceinline__ void mma16816(float* c, const uint32_t* a,
                                         const uint32_t* b) {
    asm volatile(
        "mma.sync.aligned.m16n8k16.row.col.f32.bf16.bf16.f32 "
        "{%0,%1,%2,%3}, {%4,%5,%6,%7}, {%8,%9}, {%0,%1,%2,%3};"
        : "+f"(c[0]), "+f"(c[1]), "+f"(c[2]), "+f"(c[3])
        : "r"(a[0]), "r"(a[1]), "r"(a[2]), "r"(a[3]), "r"(b[0]), "r"(b[1]));
}
__device__ __forceinline__ void split2(float r0, float r1,
                                       uint32_t& h, uint32_t& l) {
    uint32_t hp;
    asm("cvt.rn.satfinite.bf16x2.f32 %0, %1, %2;" : "=r"(hp) : "f"(r1), "f"(r0));
    float f0 = __uint_as_float(hp << 16);
    float f1 = __uint_as_float(hp & 0xFFFF0000u);
    float l0 = r0 - f0, l1 = r1 - f1;
    uint32_t lp;
    asm("cvt.rn.satfinite.bf16x2.f32 %0, %1, %2;" : "=r"(lp) : "f"(l1), "f"(l0));
    h = hp; l = lp;
}
__device__ __forceinline__ void mbar_init(uint32_t mb, uint32_t cnt) {
    asm volatile("mbarrier.init.shared.b64 [%0], %1;" :: "r"(mb), "r"(cnt)
                 : "memory");
}
__device__ __forceinline__ void mbar_arrive(uint32_t mb) {
    asm volatile("mbarrier.arrive.shared.b64 _, [%0];" :: "r"(mb) : "memory");
}
__device__ __forceinline__ void mbar_wait(uint32_t mb, uint32_t parity) {
    asm volatile(
        "{\n\t.reg .pred P1;\n\t"
        "WAIT_LOOP_%=:\n\t"
        "mbarrier.try_wait.parity.acquire.cta.shared::cta.b64 P1, [%0], %1, 0x989680;\n\t"
        "@P1 bra.uni WAIT_DONE_%=;\n\t"
        "bra.uni WAIT_LOOP_%=;\n\t"
        "WAIT_DONE_%=:\n\t}"
        :: "r"(mb), "r"(parity) : "memory");
}

// ============================================================================
// Kernel 1 (fused prep): blocks [0,1024) = feature map; rest = mid split.
// ============================================================================
__global__ void prep_kernel(const float* __restrict__ x,
                            const float* __restrict__ mid) {
    __shared__ float smc[NSITE * 8];
    __shared__ float sms[NSITE * 8];
    if (blockIdx.x < 1024) {
        int wid  = threadIdx.x >> 5;
        int lane = threadIdx.x & 31;
        int b0   = blockIdx.x * 8;
        const float* xr = x + (size_t)(b0 + wid) * NSITE;

        float v[8];
        float mn = 3.402823466e38f, mx = -3.402823466e38f;
#pragma unroll
        for (int i = 0; i < 8; i++) {
            v[i] = xr[lane + i * 32];
            mn = fminf(mn, v[i]);
            mx = fmaxf(mx, v[i]);
        }
#pragma unroll
        for (int o = 16; o; o >>= 1) {
            mn = fminf(mn, __shfl_xor_sync(0xffffffffu, mn, o));
            mx = fmaxf(mx, __shfl_xor_sync(0xffffffffu, mx, o));
        }
        float inv = 1.0f / (mx - mn + 1e-6f);
#pragma unroll
        for (int i = 0; i < 8; i++) {
            float ang = 1.57079632679f * ((v[i] - mn) * inv);
            float s, c;
            __sincosf(ang, &s, &c);
            int site = lane + i * 32;
            smc[site * 8 + wid] = c;
            sms[site * 8 + wid] = s;
        }
        __syncthreads();
#pragma unroll
        for (int i = threadIdx.x; i < NSITE * 8; i += PREP_T) {
            int site = i >> 3, o = i & 7;
            g_cos[(size_t)site * B_ + b0 + o] = smc[i];
            g_sin[(size_t)site * B_ + b0 + o] = sms[i];
        }
    } else {
        // mid split, output-centric (uint4 index == thread index)
        int idx = (blockIdx.x - 1024) * blockDim.x + threadIdx.x;
        if (idx >= NSTEP * 8192) return;
        int step = idx >> 13;
        int rem  = idx & 8191;
        int c2   = rem >> 10;          // k-chunk 0..7
        int w    = (rem >> 8) & 3;     // warp / n-strip (32 n each)
        int ldgi = (rem >> 5) & 7;     // f >> 1
        int lane = rem & 31;
        int mat = ldgi >> 2, d = (ldgi >> 1) & 1;
        int nn = lane >> 2, kq = lane & 3;

        uint32_t outv[4];
#pragma unroll
        for (int n8off = 0; n8off < 2; ++n8off)
#pragma unroll
            for (int rk = 0; rk < 2; ++rk) {
                uint32_t u = 0;
#pragma unroll
                for (int half = 0; half < 2; ++half) {
                    int n8 = (ldgi & 1) * 2 + n8off;
                    int l = c2 * 16 + rk * 8 + kq * 2 + half;
                    int n = w * 32 + n8 * 8 + nn;
                    float v = mid[(((size_t)step * 128 + l) * 2 + d) * 128 + n];
                    __nv_bfloat16 bh = __float2bfloat16(v);
                    uint16_t bits;
                    if (mat == 0) {
                        bits = *(uint16_t*)&bh;
                    } else {
                        float fh = __bfloat162float(bh);
                        __nv_bfloat16 bl = __float2bfloat16(v - fh);
                        bits = *(uint16_t*)&bl;
                    }
                    u |= (uint32_t)bits << (half * 16);
                }
                outv[n8off * 2 + rk] = u;
            }
        ((uint4*)g_B)[idx] = make_uint4(outv[0], outv[1], outv[2], outv[3]);
    }
}

// ============================================================================
// Kernel 2: HMMA MPS chain, BM=32 / 128 threads / 2 CTAs per SM.
// Each warp owns 32 n-cols = k-chunks {2wd, 2wd+1} of next step: j=0 AND j=1
// (96 MMAs) run from held epilogue registers before the split-phase wait.
// ============================================================================
__global__ void __launch_bounds__(THREADS, 2)
mps_hmma_kernel(const float* __restrict__ first,
                const float* __restrict__ last,
                const float* __restrict__ w,
                const float* __restrict__ bias,
                float* __restrict__ out) {
    extern __shared__ __align__(1024) char smem[];
    const uint32_t sb = smem_u32(smem);
    const uint32_t mb = sb + SM_MB;
    float* fl    = (float*)(smem + SM_FL);
    float* cS    = fl;            // [2][32]
    float* sS    = fl + 64;       // [2][32]
    float* c2S   = fl + 128;      // [32] site 255
    float* s2S   = fl + 160;
    float* lastS = fl + 192;      // [256]
    float* red   = fl + 448;      // [128]

    const int tid  = threadIdx.x;
    const int lane = tid & 31;
    const int wd   = tid >> 5;     // warp 0..3 = n-strip of 32 n-values
    const int gA   = lane >> 3;
    const int rowA = lane & 7;
    const int g4   = lane >> 2;
    const int q4   = lane & 3;
    const int b0   = blockIdx.x * BM;

    lastS[tid]       = __ldg(&last[tid]);
    lastS[tid + 128] = __ldg(&last[tid + 128]);

    uint4 Bb0[8], Bb1[8];
#define LOADB(R, step_, c_) do {                                             \
    const uint4* _p = (const uint4*)(g_B + (size_t)(step_) * 65536)          \
                    + ((c_) * 4 + wd) * 256 + lane;                          \
    R[0] = __ldg(_p);            R[1] = __ldg(_p + 32);                      \
    R[2] = __ldg(_p + 64);       R[3] = __ldg(_p + 96);                      \
    R[4] = __ldg(_p + 128);      R[5] = __ldg(_p + 160);                     \
    R[6] = __ldg(_p + 192);      R[7] = __ldg(_p + 224);                     \
} while (0)

    LOADB(Bb0, 0, 2 * wd);       // step-0 chunk j=0

    // ---- A0 full tile into buf 0 ----
    for (int i = tid; i < BM * D_; i += THREADS) {
        int r = i >> 7, k = i & 127;
        float c0 = __ldg(&g_cos[b0 + r]);
        float s0 = __ldg(&g_sin[b0 + r]);
        float v = __ldg(&first[k]) * c0 + __ldg(&first[D_ + k]) * s0;
        __nv_bfloat16 bh = __float2bfloat16(v);
        float fh = __bfloat162float(bh);
        __nv_bfloat16 bl = __float2bfloat16(v - fh);
        int el = ((r >> 3) * 16 + (k >> 3)) * 64 + (r & 7) * 8 + (k & 7);
        ((__nv_bfloat16*)smem)[el]        = bh;   // buf0 AH
        ((__nv_bfloat16*)smem)[4096 + el] = bl;   // buf0 AL (+8192 B)
    }

    // ---- held local A-frags for step 0: chunks 2wd, 2wd+1 ----
    uint32_t aHloc[2][8], aLloc[2][8];
#pragma unroll
    for (int mt = 0; mt < 2; ++mt) {
        int r1 = mt * 16 + g4, r2 = r1 + 8;
        float c1 = __ldg(&g_cos[b0 + r1]), s1 = __ldg(&g_sin[b0 + r1]);
        float c2_ = __ldg(&g_cos[b0 + r2]), s2_ = __ldg(&g_sin[b0 + r2]);
#pragma unroll
        for (int n8 = 0; n8 < 4; ++n8) {
            int k0 = wd * 32 + n8 * 8 + 2 * q4;
            float f0 = __ldg(&first[k0]),     g0 = __ldg(&first[128 + k0]);
            float f1 = __ldg(&first[k0 + 1]), g1 = __ldg(&first[129 + k0]);
            split2(f0 * c1 + g0 * s1, f1 * c1 + g1 * s1,
                   aHloc[mt][n8 * 2], aLloc[mt][n8 * 2]);
            split2(f0 * c2_ + g0 * s2_, f1 * c2_ + g1 * s2_,
                   aHloc[mt][n8 * 2 + 1], aLloc[mt][n8 * 2 + 1]);
        }
    }

    // pre-stage phi site 1 into slot 1
    if (tid < BM) {
        cS[32 + tid] = __ldg(&g_cos[(size_t)B_ + b0 + tid]);
        sS[32 + tid] = __ldg(&g_sin[(size_t)B_ + b0 + tid]);
    }
    if (tid == 0) mbar_init(mb, THREADS);
    __syncthreads();
    mbar_arrive(mb);             // phase 0: prologue published

#define SWEEP(AEXPR, MB_, CUR)                                               \
    _Pragma("unroll") for (int mt = 0; mt < 2; ++mt)                         \
    _Pragma("unroll") for (int d2 = 0; d2 < 2; ++d2)                         \
    _Pragma("unroll") for (int n8 = 0; n8 < 4; ++n8) {                       \
        const int f = (MB_) + d2 * 4 + n8;                                   \
        mma16816(acc[mt][d2][n8], (AEXPR),                                   \
                 (const uint32_t*)&CUR[f >> 1] + (f & 1) * 2);               \
    }

#define BODY(jv, CUR, NXT) {                                                 \
    const int c_ = (2 * wd + (jv)) & 7;                                      \
    if ((jv) < 7)             LOADB(NXT, m, (2 * wd + (jv) + 1) & 7);        \
    else if (m < NSTEP - 1)   LOADB(NXT, m + 1, 2 * wd);                     \
    uint32_t aH[2][4], aL[2][4];                                             \
    _Pragma("unroll") for (int mt = 0; mt < 2; ++mt) {                       \
        uint32_t off = (uint32_t)(((mt * 2 + (gA & 1)) * 16 +                \
                       (c_ * 2 + (gA >> 1))) * 128 + rowA * 16);             \
        ldsm4(aH[mt], sb + acur + off);                                      \
        ldsm4(aL[mt], sb + acur + 8192 + off);                               \
    }                                                                        \
    SWEEP(aH[mt], 0, CUR)                                                    \
    SWEEP(aL[mt], 0, CUR)                                                    \
    SWEEP(aH[mt], 8, CUR)                                                    \
}

    // ---- site loop: split-phase barrier per step ----
#pragma unroll 1
    for (int m = 0; m < NSTEP; ++m) {
        const uint32_t acur = (uint32_t)((m & 1) * 16384);
        const uint32_t anxt = acur ^ 16384u;

        float acc[2][2][4][4];
#pragma unroll
        for (int mt = 0; mt < 2; ++mt)
#pragma unroll
            for (int d2 = 0; d2 < 2; ++d2)
#pragma unroll
                for (int n8 = 0; n8 < 4; ++n8)
#pragma unroll
                    for (int q = 0; q < 4; ++q) acc[mt][d2][n8][q] = 0.0f;

        // j=0 from held registers
        LOADB(Bb1, m, (2 * wd + 1) & 7);
        SWEEP(aHloc[mt], 0, Bb0)
        SWEEP(aLloc[mt], 0, Bb0)
        SWEEP(aHloc[mt], 8, Bb0)

        // j=1 from held registers
        LOADB(Bb0, m, (2 * wd + 2) & 7);
        SWEEP(aHloc[mt] + 4, 0, Bb1)
        SWEEP(aLloc[mt] + 4, 0, Bb1)
        SWEEP(aHloc[mt] + 4, 8, Bb1)

        // wait: all warps' previous-step epilogues published
        mbar_wait(mb, (uint32_t)(m & 1));

        // stage phi site m+2 into slot m&1 (safe post-wait)
        if (tid < BM) {
            cS[(m & 1) * 32 + tid] =
                __ldg(&g_cos[(size_t)(m + 2) * B_ + b0 + tid]);
            sS[(m & 1) * 32 + tid] =
                __ldg(&g_sin[(size_t)(m + 2) * B_ + b0 + tid]);
        }
        if (m == NSTEP - 2 && tid >= 32 && tid < 64) {
            int t = tid - 32;
            c2S[t] = __ldg(&g_cos[(size_t)(NSITE - 1) * B_ + b0 + t]);
            s2S[t] = __ldg(&g_sin[(size_t)(NSITE - 1) * B_ + b0 + t]);
        }

        BODY(2, Bb0, Bb1)
        BODY(3, Bb1, Bb0)
        BODY(4, Bb0, Bb1)
        BODY(5, Bb1, Bb0)
        BODY(6, Bb0, Bb1)
        BODY(7, Bb1, Bb0)

        const int slot = ((m + 1) & 1) * 32;
        if (m < NSTEP - 1) {
            // ---- epilogue: combine parity, split hi/lo; hold frags; stsm ----
#pragma unroll
            for (int mt = 0; mt < 2; ++mt) {
                float cl = cS[slot + mt * 16 + g4];
                float ch = cS[slot + mt * 16 + g4 + 8];
                float sl = sS[slot + mt * 16 + g4];
                float sh = sS[slot + mt * 16 + g4 + 8];
#pragma unroll
                for (int n8 = 0; n8 < 4; ++n8) {
                    float* E = acc[mt][0][n8];
                    float* O = acc[mt][1][n8];
                    split2(cl * E[0] + sl * O[0], cl * E[1] + sl * O[1],
                           aHloc[mt][n8 * 2], aLloc[mt][n8 * 2]);
                    split2(ch * E[2] + sh * O[2], ch * E[3] + sh * O[3],
                           aHloc[mt][n8 * 2 + 1], aLloc[mt][n8 * 2 + 1]);
                }
#pragma unroll
                for (int ktl = 0; ktl < 2; ++ktl) {
                    uint32_t off = (uint32_t)(((mt * 2 + (gA & 1)) * 16 +
                        (wd * 4 + ktl * 2 + (gA >> 1))) * 128 + rowA * 16);
                    stsm4(sb + anxt + off,
                          aHloc[mt][ktl * 4], aHloc[mt][ktl * 4 + 1],
                          aHloc[mt][ktl * 4 + 2], aHloc[mt][ktl * 4 + 3]);
                    stsm4(sb + anxt + 8192 + off,
                          aLloc[mt][ktl * 4], aLloc[mt][ktl * 4 + 1],
                          aLloc[mt][ktl * 4 + 2], aLloc[mt][ktl * 4 + 3]);
                }
            }
            mbar_arrive(mb);
        } else {
            // ---- final: contract with last site + linear head ----
            float part[2][2] = {{0.f, 0.f}, {0.f, 0.f}};
#pragma unroll
            for (int mt = 0; mt < 2; ++mt) {
                float cl = cS[slot + mt * 16 + g4];
                float ch = cS[slot + mt * 16 + g4 + 8];
                float sl = sS[slot + mt * 16 + g4];
                float sh = sS[slot + mt * 16 + g4 + 8];
                float c2l = c2S[mt * 16 + g4], c2h = c2S[mt * 16 + g4 + 8];
                float s2l = s2S[mt * 16 + g4], s2h = s2S[mt * 16 + g4 + 8];
#pragma unroll
                for (int n8 = 0; n8 < 4; ++n8) {
                    float* E = acc[mt][0][n8];
                    float* O = acc[mt][1][n8];
                    int n0 = wd * 32 + n8 * 8 + 2 * q4;
                    float w0l = lastS[2 * n0] * c2l + lastS[2 * n0 + 1] * s2l;
                    float w1l = lastS[2 * n0 + 2] * c2l + lastS[2 * n0 + 3] * s2l;
                    float w0h = lastS[2 * n0] * c2h + lastS[2 * n0 + 1] * s2h;
                    float w1h = lastS[2 * n0 + 2] * c2h + lastS[2 * n0 + 3] * s2h;
                    part[mt][0] += (cl * E[0] + sl * O[0]) * w0l
                                 + (cl * E[1] + sl * O[1]) * w1l;
                    part[mt][1] += (ch * E[2] + sh * O[2]) * w0h
                                 + (ch * E[3] + sh * O[3]) * w1h;
                }
            }
#pragma unroll
            for (int o = 1; o <= 2; o <<= 1)
#pragma unroll
                for (int mt = 0; mt < 2; ++mt) {
                    part[mt][0] += __shfl_xor_sync(0xffffffffu, part[mt][0], o);
                    part[mt][1] += __shfl_xor_sync(0xffffffffu, part[mt][1], o);
                }
            if (q4 == 0) {
#pragma unroll
                for (int mt = 0; mt < 2; ++mt) {
                    red[wd * 32 + mt * 16 + g4]     = part[mt][0];
                    red[wd * 32 + mt * 16 + g4 + 8] = part[mt][1];
                }
            }
            __syncthreads();
            if (tid < BM) {
                float tot = red[tid] + red[32 + tid] + red[64 + tid]
                          + red[96 + tid];
#pragma unroll
                for (int o = 0; o < OUT_; ++o)
                    out[(size_t)(b0 + tid) * OUT_ + o] =
                        tot * __ldg(&w[o]) + __ldg(&bias[o]);
            }
        }
    }
#undef BODY
#undef SWEEP
#undef LOADB
}

// ============================================================================
// Launch: 2 kernels.
// ============================================================================
extern "C" void kernel_launch(void* const* d_in, const int* in_sizes, int n_in,
                              void* d_out, int out_size) {
    const float* x     = (const float*)d_in[0];  // [B, N]
    const float* first = (const float*)d_in[1];  // [1, 2, D]
    const float* mid   = (const float*)d_in[2];  // [N-2, D, 2, D]
    const float* last  = (const float*)d_in[3];  // [D, 2, 1]
    const float* w     = (const float*)d_in[4];  // [OUT, 1]
    const float* bias  = (const float*)d_in[5];  // [OUT]
    float* out = (float*)d_out;                  // [B, OUT]

    cudaFuncSetAttribute(mps_hmma_kernel,
                         cudaFuncAttributeMaxDynamicSharedMemorySize,
                         SMEM_TOTAL);

    prep_kernel<<<1024 + (NSTEP * 8192 + PREP_T - 1) / PREP_T, PREP_T>>>(x, mid);
    mps_hmma_kernel<<<NCTA, THREADS, SMEM_TOTAL>>>(first, last, w, bias, out);
}

// round 12
// speedup vs baseline: 1.0465x; 1.0465x over previous
#include <cuda_runtime.h>
#include <cuda_bf16.h>
#include <cstdint>

// Problem constants
#define B_     8192
#define NSITE  256
#define D_     128
#define OUT_   10
#define NSTEP  254
#define BM     64            // samples per CTA
#define NCTA   (B_ / BM)     // 128 CTAs, 1 per SM
#define THREADS 512          // 16 warps: 2 M-strips x 8 N-strips
#define PREP_T  256

// Dynamic smem layout (bytes): A double-buffer (2 x 32KB) + staging + mbar
#define SM_FL   65536
#define SM_MB   (SM_FL + 4608)
#define SMEM_TOTAL (SM_MB + 16)

// Scratch globals
__device__ float g_cos[NSITE * B_];                      // 8 MB
__device__ float g_sin[NSITE * B_];                      // 8 MB
// Fragment-major pre-split B (R10 layout): per step 8192 uint4 chunks:
// uint4 index = [step:*][c2:3][w:3][ldg:2][lane:5]  (ldg = mat*2 + parity)
__device__ __nv_bfloat16 g_B[(size_t)NSTEP * 65536];     // 33.3 MB

// ---------------------------------------------------------------------------
// Base-ISA asm helpers
// ---------------------------------------------------------------------------
__device__ __forceinline__ uint32_t smem_u32(const void* p) {
    uint32_t a;
    asm("{ .reg .u64 t; cvta.to.shared.u64 t, %1; cvt.u32.u64 %0, t; }"
        : "=r"(a) : "l"(p));
    return a;
}
__device__ __forceinline__ void ldsm4(uint32_t* r, uint32_t a) {
    asm volatile("ldmatrix.sync.aligned.m8n8.x4.shared.b16 {%0,%1,%2,%3}, [%4];"
                 : "=r"(r[0]), "=r"(r[1]), "=r"(r[2]), "=r"(r[3]) : "r"(a));
}
__device__ __forceinline__ void stsm4(uint32_t a, uint32_t r0, uint32_t r1,
                                      uint32_t r2, uint32_t r3) {
    asm volatile("stmatrix.sync.aligned.m8n8.x4.shared.b16 [%0], {%1,%2,%3,%4};"
                 :: "r"(a), "r"(r0), "r"(r1), "r"(r2), "r"(r3) : "memory");
}
__device__ __forceinline__ void mma16816(float* c, const uint32_t* a,
                                         const uint32_t* b) {
    asm volatile(
        "mma.sync.aligned.m16n8k16.row.col.f32.bf16.bf16.f32 "
        "{%0,%1,%2,%3}, {%4,%5,%6,%7}, {%8,%9}, {%0,%1,%2,%3};"
        : "+f"(c[0]), "+f"(c[1]), "+f"(c[2]), "+f"(c[3])
        : "r"(a[0]), "r"(a[1]), "r"(a[2]), "r"(a[3]), "r"(b[0]), "r"(b[1]));
}
__device__ __forceinline__ void split2(float r0, float r1,
                                       uint32_t& h, uint32_t& l) {
    uint32_t hp;
    asm("cvt.rn.satfinite.bf16x2.f32 %0, %1, %2;" : "=r"(hp) : "f"(r1), "f"(r0));
    float f0 = __uint_as_float(hp << 16);
    float f1 = __uint_as_float(hp & 0xFFFF0000u);
    float l0 = r0 - f0, l1 = r1 - f1;
    uint32_t lp;
    asm("cvt.rn.satfinite.bf16x2.f32 %0, %1, %2;" : "=r"(lp) : "f"(l1), "f"(l0));
    h = hp; l = lp;
}
__device__ __forceinline__ void mbar_init(uint32_t mb, uint32_t cnt) {
    asm volatile("mbarrier.init.shared.b64 [%0], %1;" :: "r"(mb), "r"(cnt)
                 : "memory");
}
__device__ __forceinline__ void mbar_arrive(uint32_t mb) {
    asm volatile("mbarrier.arrive.shared.b64 _, [%0];" :: "r"(mb) : "memory");
}
__device__ __forceinline__ void mbar_wait(uint32_t mb, uint32_t parity) {
    asm volatile(
        "{\n\t.reg .pred P1;\n\t"
        "WAIT_LOOP_%=:\n\t"
        "mbarrier.try_wait.parity.acquire.cta.shared::cta.b64 P1, [%0], %1, 0x989680;\n\t"
        "@P1 bra.uni WAIT_DONE_%=;\n\t"
        "bra.uni WAIT_LOOP_%=;\n\t"
        "WAIT_DONE_%=:\n\t}"
        :: "r"(mb), "r"(parity) : "memory");
}

// ============================================================================
// Kernel 1 (fused prep): blocks [0,1024) = feature map; rest = mid split
// (identical to R10 layout).
// ============================================================================
__global__ void prep_kernel(const float* __restrict__ x,
                            const float* __restrict__ mid) {
    __shared__ float smc[NSITE * 8];
    __shared__ float sms[NSITE * 8];
    if (blockIdx.x < 1024) {
        int wid  = threadIdx.x >> 5;
        int lane = threadIdx.x & 31;
        int b0   = blockIdx.x * 8;
        const float* xr = x + (size_t)(b0 + wid) * NSITE;

        float v[8];
        float mn = 3.402823466e38f, mx = -3.402823466e38f;
#pragma unroll
        for (int i = 0; i < 8; i++) {
            v[i] = xr[lane + i * 32];
            mn = fminf(mn, v[i]);
            mx = fmaxf(mx, v[i]);
        }
#pragma unroll
        for (int o = 16; o; o >>= 1) {
            mn = fminf(mn, __shfl_xor_sync(0xffffffffu, mn, o));
            mx = fmaxf(mx, __shfl_xor_sync(0xffffffffu, mx, o));
        }
        float inv = 1.0f / (mx - mn + 1e-6f);
#pragma unroll
        for (int i = 0; i < 8; i++) {
            float ang = 1.57079632679f * ((v[i] - mn) * inv);
            float s, c;
            __sincosf(ang, &s, &c);
            int site = lane + i * 32;
            smc[site * 8 + wid] = c;
            sms[site * 8 + wid] = s;
        }
        __syncthreads();
#pragma unroll
        for (int i = threadIdx.x; i < NSITE * 8; i += PREP_T) {
            int site = i >> 3, o = i & 7;
            g_cos[(size_t)site * B_ + b0 + o] = smc[i];
            g_sin[(size_t)site * B_ + b0 + o] = sms[i];
        }
    } else {
        int idx = (blockIdx.x - 1024) * blockDim.x + threadIdx.x;
        if (idx >= NSTEP * 8192) return;
        int step = idx >> 13;
        int rem  = idx & 8191;
        int c2   = rem >> 10;
        int w    = (rem >> 7) & 7;
        int ldgi = (rem >> 5) & 3;
        int lane = rem & 31;
        int mat = ldgi >> 1, d = ldgi & 1;
        int nn = lane >> 2, kq = lane & 3;

        uint32_t outv[4];
#pragma unroll
        for (int n8 = 0; n8 < 2; ++n8)
#pragma unroll
            for (int rk = 0; rk < 2; ++rk) {
                uint32_t u = 0;
#pragma unroll
                for (int half = 0; half < 2; ++half) {
                    int l = c2 * 16 + rk * 8 + kq * 2 + half;
                    int n = w * 16 + n8 * 8 + nn;
                    float v = mid[(((size_t)step * 128 + l) * 2 + d) * 128 + n];
                    __nv_bfloat16 bh = __float2bfloat16(v);
                    uint16_t bits;
                    if (mat == 0) {
                        bits = *(uint16_t*)&bh;
                    } else {
                        float fh = __bfloat162float(bh);
                        __nv_bfloat16 bl = __float2bfloat16(v - fh);
                        bits = *(uint16_t*)&bl;
                    }
                    u |= (uint32_t)bits << (half * 16);
                }
                outv[n8 * 2 + rk] = u;
            }
        ((uint4*)g_B)[idx] = make_uint4(outv[0], outv[1], outv[2], outv[3]);
    }
}

// ============================================================================
// Kernel 2: HMMA MPS chain, 16 warps (2 M-strips x 8 N-strips), 1 CTA/SM.
// 4 independent warp chains per SMSP hide ldsm/epilogue/barrier latency.
// Warp (mw, nw) owns rows [mw*32, mw*32+32), n-cols [nw*16, nw*16+16).
// j=0 chunk (c = nw) runs from held epilogue registers before the wait.
// ============================================================================
__global__ void __launch_bounds__(THREADS, 1)
mps_hmma_kernel(const float* __restrict__ first,
                const float* __restrict__ last,
                const float* __restrict__ w,
                const float* __restrict__ bias,
                float* __restrict__ out) {
    extern __shared__ __align__(1024) char smem[];
    const uint32_t sb = smem_u32(smem);
    const uint32_t mb = sb + SM_MB;
    float* fl    = (float*)(smem + SM_FL);
    float* cS    = fl;            // [2][64]
    float* sS    = fl + 128;      // [2][64]
    float* c2S   = fl + 256;      // [64] site 255
    float* s2S   = fl + 320;
    float* lastS = fl + 384;      // [256]
    float* red   = fl + 640;      // [8][64]

    const int tid  = threadIdx.x;
    const int lane = tid & 31;
    const int wid  = tid >> 5;
    const int nw   = wid & 7;      // n-strip (16 n-cols)
    const int mw   = wid >> 3;     // m-strip (32 rows)
    const int gA   = lane >> 3;
    const int rowA = lane & 7;
    const int g4   = lane >> 2;
    const int q4   = lane & 3;
    const int b0   = blockIdx.x * BM;

    if (tid < 256) lastS[tid] = __ldg(&last[tid]);

    uint4 Bb0[4], Bb1[4];
#define LOADB(R, step_, c_) do {                                             \
    const uint4* _p = (const uint4*)(g_B + (size_t)(step_) * 65536)          \
                    + ((c_) * 8 + nw) * 128 + lane;                          \
    R[0] = __ldg(_p); R[1] = __ldg(_p + 32);                                 \
    R[2] = __ldg(_p + 64); R[3] = __ldg(_p + 96);                            \
} while (0)

    LOADB(Bb0, 0, nw);

    // ---- A0 full tile into buf 0 ----
    for (int i = tid; i < BM * D_; i += THREADS) {
        int r = i >> 7, k = i & 127;
        float c0 = __ldg(&g_cos[b0 + r]);
        float s0 = __ldg(&g_sin[b0 + r]);
        float v = __ldg(&first[k]) * c0 + __ldg(&first[D_ + k]) * s0;
        __nv_bfloat16 bh = __float2bfloat16(v);
        float fh = __bfloat162float(bh);
        __nv_bfloat16 bl = __float2bfloat16(v - fh);
        int el = ((r >> 3) * 16 + (k >> 3)) * 64 + (r & 7) * 8 + (k & 7);
        ((__nv_bfloat16*)smem)[el]        = bh;
        ((__nv_bfloat16*)smem)[8192 + el] = bl;
    }

    // ---- held local A-frags for step 0 (chunk nw, this warp's rows) ----
    uint32_t aHloc[2][4], aLloc[2][4];
#pragma unroll
    for (int mt = 0; mt < 2; ++mt) {
        int r1 = (mw * 2 + mt) * 16 + g4, r2 = r1 + 8;
        float c1 = __ldg(&g_cos[b0 + r1]), s1 = __ldg(&g_sin[b0 + r1]);
        float c2_ = __ldg(&g_cos[b0 + r2]), s2_ = __ldg(&g_sin[b0 + r2]);
#pragma unroll
        for (int n8 = 0; n8 < 2; ++n8) {
            int k0 = nw * 16 + n8 * 8 + 2 * q4;
            float f0 = __ldg(&first[k0]),     g0 = __ldg(&first[128 + k0]);
            float f1 = __ldg(&first[k0 + 1]), g1 = __ldg(&first[129 + k0]);
            split2(f0 * c1 + g0 * s1, f1 * c1 + g1 * s1,
                   aHloc[mt][n8 * 2], aLloc[mt][n8 * 2]);
            split2(f0 * c2_ + g0 * s2_, f1 * c2_ + g1 * s2_,
                   aHloc[mt][n8 * 2 + 1], aLloc[mt][n8 * 2 + 1]);
        }
    }

    // pre-stage phi site 1 into slot 1
    if (tid < BM) {
        cS[64 + tid] = __ldg(&g_cos[(size_t)B_ + b0 + tid]);
        sS[64 + tid] = __ldg(&g_sin[(size_t)B_ + b0 + tid]);
    }
    if (tid == 0) mbar_init(mb, THREADS);
    __syncthreads();
    mbar_arrive(mb);             // phase 0: prologue published

#define SWEEP(AF, MB_, CUR)                                                  \
    _Pragma("unroll") for (int mt = 0; mt < 2; ++mt)                         \
    _Pragma("unroll") for (int d2 = 0; d2 < 2; ++d2)                         \
    _Pragma("unroll") for (int n8 = 0; n8 < 2; ++n8) {                       \
        const int f = (MB_) + d2 * 2 + n8;                                   \
        mma16816(acc[mt][d2][n8], AF[mt],                                    \
                 (const uint32_t*)&CUR[f >> 1] + (f & 1) * 2);               \
    }

#define BODY(jv, CUR, NXT) {                                                 \
    const int c_ = (nw + (jv)) & 7;                                          \
    if ((jv) < 7)             LOADB(NXT, m, (nw + (jv) + 1) & 7);            \
    else if (m < NSTEP - 1)   LOADB(NXT, m + 1, nw);                         \
    uint32_t aH[2][4], aL[2][4];                                             \
    _Pragma("unroll") for (int mt = 0; mt < 2; ++mt) {                       \
        uint32_t off = (uint32_t)(((mw * 4 + mt * 2 + (gA & 1)) * 16 +       \
                       (c_ * 2 + (gA >> 1))) * 128 + rowA * 16);             \
        ldsm4(aH[mt], sb + acur + off);                                      \
        ldsm4(aL[mt], sb + acur + 16384 + off);                              \
    }                                                                        \
    SWEEP(aH, 0, CUR)                                                        \
    SWEEP(aL, 0, CUR)                                                        \
    SWEEP(aH, 4, CUR)                                                        \
}

    // ---- site loop: split-phase barrier per step ----
#pragma unroll 1
    for (int m = 0; m < NSTEP; ++m) {
        const uint32_t acur = (uint32_t)((m & 1) * 32768);
        const uint32_t anxt = acur ^ 32768u;

        float acc[2][2][2][4];
#pragma unroll
        for (int mt = 0; mt < 2; ++mt)
#pragma unroll
            for (int d2 = 0; d2 < 2; ++d2)
#pragma unroll
                for (int n8 = 0; n8 < 2; ++n8)
#pragma unroll
                    for (int q = 0; q < 4; ++q) acc[mt][d2][n8][q] = 0.0f;

        // j=0 from held registers (chunk nw)
        LOADB(Bb1, m, (nw + 1) & 7);
        SWEEP(aHloc, 0, Bb0)
        SWEEP(aLloc, 0, Bb0)
        SWEEP(aHloc, 4, Bb0)

        // wait: all warps' previous-step epilogues published
        mbar_wait(mb, (uint32_t)(m & 1));

        // stage phi site m+2 into slot m&1 (safe post-wait)
        if (tid < BM) {
            cS[(m & 1) * 64 + tid] =
                __ldg(&g_cos[(size_t)(m + 2) * B_ + b0 + tid]);
            sS[(m & 1) * 64 + tid] =
                __ldg(&g_sin[(size_t)(m + 2) * B_ + b0 + tid]);
        }
        if (m == NSTEP - 2 && tid >= 64 && tid < 128) {
            int t = tid - 64;
            c2S[t] = __ldg(&g_cos[(size_t)(NSITE - 1) * B_ + b0 + t]);
            s2S[t] = __ldg(&g_sin[(size_t)(NSITE - 1) * B_ + b0 + t]);
        }

        BODY(1, Bb1, Bb0)
        BODY(2, Bb0, Bb1)
        BODY(3, Bb1, Bb0)
        BODY(4, Bb0, Bb1)
        BODY(5, Bb1, Bb0)
        BODY(6, Bb0, Bb1)
        BODY(7, Bb1, Bb0)

        const int slot = ((m + 1) & 1) * 64;
        if (m < NSTEP - 1) {
            // ---- epilogue: combine parity, split hi/lo; hold frags; stsm ----
#pragma unroll
            for (int mt = 0; mt < 2; ++mt) {
                int rb = (mw * 2 + mt) * 16 + g4;
                float cl = cS[slot + rb], ch = cS[slot + rb + 8];
                float sl = sS[slot + rb], sh = sS[slot + rb + 8];
#pragma unroll
                for (int n8 = 0; n8 < 2; ++n8) {
                    float* E = acc[mt][0][n8];
                    float* O = acc[mt][1][n8];
                    split2(cl * E[0] + sl * O[0], cl * E[1] + sl * O[1],
                           aHloc[mt][n8 * 2], aLloc[mt][n8 * 2]);
                    split2(ch * E[2] + sh * O[2], ch * E[3] + sh * O[3],
                           aHloc[mt][n8 * 2 + 1], aLloc[mt][n8 * 2 + 1]);
                }
                uint32_t off = (uint32_t)(((mw * 4 + mt * 2 + (gA & 1)) * 16 +
                               (nw * 2 + (gA >> 1))) * 128 + rowA * 16);
                stsm4(sb + anxt + off, aHloc[mt][0], aHloc[mt][1],
                      aHloc[mt][2], aHloc[mt][3]);
                stsm4(sb + anxt + 16384 + off, aLloc[mt][0], aLloc[mt][1],
                      aLloc[mt][2], aLloc[mt][3]);
            }
            mbar_arrive(mb);
        } else {
            // ---- final: contract with last site + linear head ----
            float part[2][2] = {{0.f, 0.f}, {0.f, 0.f}};
#pragma unroll
            for (int mt = 0; mt < 2; ++mt) {
                int rb = (mw * 2 + mt) * 16 + g4;
                float cl = cS[slot + rb], ch = cS[slot + rb + 8];
                float sl = sS[slot + rb], sh = sS[slot + rb + 8];
                float c2l = c2S[rb], c2h = c2S[rb + 8];
                float s2l = s2S[rb], s2h = s2S[rb + 8];
#pragma unroll
                for (int n8 = 0; n8 < 2; ++n8) {
                    float* E = acc[mt][0][n8];
                    float* O = acc[mt][1][n8];
                    int n0 = nw * 16 + n8 * 8 + 2 * q4;
                    float w0l = lastS[2 * n0] * c2l + lastS[2 * n0 + 1] * s2l;
                    float w1l = lastS[2 * n0 + 2] * c2l + lastS[2 * n0 + 3] * s2l;
                    float w0h = lastS[2 * n0] * c2h + lastS[2 * n0 + 1] * s2h;
                    float w1h = lastS[2 * n0 + 2] * c2h + lastS[2 * n0 + 3] * s2h;
                    part[mt][0] += (cl * E[0] + sl * O[0]) * w0l
                                 + (cl * E[1] + sl * O[1]) * w1l;
                    part[mt][1] += (ch * E[2] + sh * O[2]) * w0h
                                 + (ch * E[3] + sh * O[3]) * w1h;
                }
            }
#pragma unroll
            for (int o = 1; o <= 2; o <<= 1)
#pragma unroll
                for (int mt = 0; mt < 2; ++mt) {
                    part[mt][0] += __shfl_xor_sync(0xffffffffu, part[mt][0], o);
                    part[mt][1] += __shfl_xor_sync(0xffffffffu, part[mt][1], o);
                }
            if (q4 == 0) {
#pragma unroll
                for (int mt = 0; mt < 2; ++mt) {
                    int rb = (mw * 2 + mt) * 16 + g4;
                    red[nw * 64 + rb]     = part[mt][0];
                    red[nw * 64 + rb + 8] = part[mt][1];
                }
            }
            __syncthreads();
            if (tid < BM) {
                float tot = 0.f;
#pragma unroll
                for (int ww = 0; ww < 8; ++ww) tot += red[ww * 64 + tid];
#pragma unroll
                for (int o = 0; o < OUT_; ++o)
                    out[(size_t)(b0 + tid) * OUT_ + o] =
                        tot * __ldg(&w[o]) + __ldg(&bias[o]);
            }
        }
    }
#undef BODY
#undef SWEEP
#undef LOADB
}

// ============================================================================
// Launch: 2 kernels.
// ============================================================================
extern "C" void kernel_launch(void* const* d_in, const int* in_sizes, int n_in,
                              void* d_out, int out_size) {
    const float* x     = (const float*)d_in[0];  // [B, N]
    const float* first = (const float*)d_in[1];  // [1, 2, D]
    const float* mid   = (const float*)d_in[2];  // [N-2, D, 2, D]
    const float* last  = (const float*)d_in[3];  // [D, 2, 1]
    const float* w     = (const float*)d_in[4];  // [OUT, 1]
    const float* bias  = (const float*)d_in[5];  // [OUT]
    float* out = (float*)d_out;                  // [B, OUT]

    cudaFuncSetAttribute(mps_hmma_kernel,
                         cudaFuncAttributeMaxDynamicSharedMemorySize,
                         SMEM_TOTAL);

    prep_kernel<<<1024 + (NSTEP * 8192 + PREP_T - 1) / PREP_T, PREP_T>>>(x, mid);
    mps_hmma_kernel<<<NCTA, THREADS, SMEM_TOTAL>>>(first, last, w, bias, out);
}

// round 13
// speedup vs baseline: 1.1038x; 1.0547x over previous
#include <cuda_runtime.h>
#include <cuda_bf16.h>
#include <cstdint>

// Problem constants
#define B_     8192
#define NSITE  256
#define D_     128
#define OUT_   10
#define NSTEP  254
#define BM     64            // samples per CTA
#define NCTA   (B_ / BM)     // 128 CTAs, 1 per SM
#define THREADS 256          // 8 warps, N-split only
#define PREP_T  256

// Dynamic smem layout (bytes): A double-buffer + staging + mbarrier
#define SM_FL   65536        // float staging area begins here
#define SM_MB   (SM_FL + 4608)
#define SMEM_TOTAL (SM_MB + 16)

// Scratch globals
__device__ float g_cos[NSITE * B_];                      // 8 MB
__device__ float g_sin[NSITE * B_];                      // 8 MB
// Fragment-major pre-split B: per step 8192 uint4 chunks laid out so that
// uint4 index = [step:*][c2:3][w:3][ldg:2][lane:5]  (ldg = mat*2 + parity)
__device__ __nv_bfloat16 g_B[(size_t)NSTEP * 65536];     // 33.3 MB

// ---------------------------------------------------------------------------
// Base-ISA asm helpers
// ---------------------------------------------------------------------------
__device__ __forceinline__ uint32_t smem_u32(const void* p) {
    uint32_t a;
    asm("{ .reg .u64 t; cvta.to.shared.u64 t, %1; cvt.u32.u64 %0, t; }"
        : "=r"(a) : "l"(p));
    return a;
}
__device__ __forceinline__ void ldsm4(uint32_t* r, uint32_t a) {
    asm volatile("ldmatrix.sync.aligned.m8n8.x4.shared.b16 {%0,%1,%2,%3}, [%4];"
                 : "=r"(r[0]), "=r"(r[1]), "=r"(r[2]), "=r"(r[3]) : "r"(a));
}
__device__ __forceinline__ void stsm4(uint32_t a, uint32_t r0, uint32_t r1,
                                      uint32_t r2, uint32_t r3) {
    asm volatile("stmatrix.sync.aligned.m8n8.x4.shared.b16 [%0], {%1,%2,%3,%4};"
                 :: "r"(a), "r"(r0), "r"(r1), "r"(r2), "r"(r3) : "memory");
}
__device__ __forceinline__ void mma16816(float* c, const uint32_t* a,
                                         const uint32_t* b) {
    asm volatile(
        "mma.sync.aligned.m16n8k16.row.col.f32.bf16.bf16.f32 "
        "{%0,%1,%2,%3}, {%4,%5,%6,%7}, {%8,%9}, {%0,%1,%2,%3};"
        : "+f"(c[0]), "+f"(c[1]), "+f"(c[2]), "+f"(c[3])
        : "r"(a[0]), "r"(a[1]), "r"(a[2]), "r"(a[3]), "r"(b[0]), "r"(b[1]));
}
__device__ __forceinline__ void split2(float r0, float r1,
                                       uint32_t& h, uint32_t& l) {
    uint32_t hp;
    asm("cvt.rn.satfinite.bf16x2.f32 %0, %1, %2;" : "=r"(hp) : "f"(r1), "f"(r0));
    float f0 = __uint_as_float(hp << 16);
    float f1 = __uint_as_float(hp & 0xFFFF0000u);
    float l0 = r0 - f0, l1 = r1 - f1;
    uint32_t lp;
    asm("cvt.rn.satfinite.bf16x2.f32 %0, %1, %2;" : "=r"(lp) : "f"(l1), "f"(l0));
    h = hp; l = lp;
}
__device__ __forceinline__ void mbar_init(uint32_t mb, uint32_t cnt) {
    asm volatile("mbarrier.init.shared.b64 [%0], %1;" :: "r"(mb), "r"(cnt)
                 : "memory");
}
__device__ __forceinline__ void mbar_arrive(uint32_t mb) {
    asm volatile("mbarrier.arrive.shared.b64 _, [%0];" :: "r"(mb) : "memory");
}
__device__ __forceinline__ void mbar_wait(uint32_t mb, uint32_t parity) {
    asm volatile(
        "{\n\t.reg .pred P1;\n\t"
        "WAIT_LOOP_%=:\n\t"
        "mbarrier.try_wait.parity.acquire.cta.shared::cta.b64 P1, [%0], %1, 0x989680;\n\t"
        "@P1 bra.uni WAIT_DONE_%=;\n\t"
        "bra.uni WAIT_LOOP_%=;\n\t"
        "WAIT_DONE_%=:\n\t}"
        :: "r"(mb), "r"(parity) : "memory");
}

// ============================================================================
// Kernel 1 (fused prep): blocks [0,1024) = feature map; rest = mid split.
// ============================================================================
__global__ void prep_kernel(const float* __restrict__ x,
                            const float* __restrict__ mid) {
    __shared__ float smc[NSITE * 8];
    __shared__ float sms[NSITE * 8];
    if (blockIdx.x < 1024) {
        int wid  = threadIdx.x >> 5;
        int lane = threadIdx.x & 31;
        int b0   = blockIdx.x * 8;
        const float* xr = x + (size_t)(b0 + wid) * NSITE;

        float v[8];
        float mn = 3.402823466e38f, mx = -3.402823466e38f;
#pragma unroll
        for (int i = 0; i < 8; i++) {
            v[i] = xr[lane + i * 32];
            mn = fminf(mn, v[i]);
            mx = fmaxf(mx, v[i]);
        }
#pragma unroll
        for (int o = 16; o; o >>= 1) {
            mn = fminf(mn, __shfl_xor_sync(0xffffffffu, mn, o));
            mx = fmaxf(mx, __shfl_xor_sync(0xffffffffu, mx, o));
        }
        float inv = 1.0f / (mx - mn + 1e-6f);
#pragma unroll
        for (int i = 0; i < 8; i++) {
            float ang = 1.57079632679f * ((v[i] - mn) * inv);
            float s, c;
            __sincosf(ang, &s, &c);
            int site = lane + i * 32;
            smc[site * 8 + wid] = c;
            sms[site * 8 + wid] = s;
        }
        __syncthreads();
#pragma unroll
        for (int i = threadIdx.x; i < NSITE * 8; i += PREP_T) {
            int site = i >> 3, o = i & 7;
            g_cos[(size_t)site * B_ + b0 + o] = smc[i];
            g_sin[(size_t)site * B_ + b0 + o] = sms[i];
        }
    } else {
        // mid split, output-centric (uint4 index == thread index)
        int idx = (blockIdx.x - 1024) * blockDim.x + threadIdx.x;
        if (idx >= NSTEP * 8192) return;
        int step = idx >> 13;
        int rem  = idx & 8191;
        int c2   = rem >> 10;
        int w    = (rem >> 7) & 7;
        int ldgi = (rem >> 5) & 3;
        int lane = rem & 31;
        int mat = ldgi >> 1, d = ldgi & 1;
        int nn = lane >> 2, kq = lane & 3;

        uint32_t outv[4];
#pragma unroll
        for (int n8 = 0; n8 < 2; ++n8)
#pragma unroll
            for (int rk = 0; rk < 2; ++rk) {
                uint32_t u = 0;
#pragma unroll
                for (int half = 0; half < 2; ++half) {
                    int l = c2 * 16 + rk * 8 + kq * 2 + half;
                    int n = w * 16 + n8 * 8 + nn;
                    float v = mid[(((size_t)step * 128 + l) * 2 + d) * 128 + n];
                    __nv_bfloat16 bh = __float2bfloat16(v);
                    uint16_t bits;
                    if (mat == 0) {
                        bits = *(uint16_t*)&bh;
                    } else {
                        float fh = __bfloat162float(bh);
                        __nv_bfloat16 bl = __float2bfloat16(v - fh);
                        bits = *(uint16_t*)&bl;
                    }
                    u |= (uint32_t)bits << (half * 16);
                }
                outv[n8 * 2 + rk] = u;
            }
        ((uint4*)g_B)[idx] = make_uint4(outv[0], outv[1], outv[2], outv[3]);
    }
}

// ============================================================================
// Kernel 2: HMMA MPS chain (R10 structure: 8 warps, BM=64, split-phase
// mbarrier, j=0 from held registers). NEW: j=7's MMA sweeps are fused
// per-m-tile with that tile's epilogue (parity-combine + split + stsm), so
// the fma-pipe epilogue overlaps the tensor-pipe MMAs at the step tail.
// ============================================================================
__global__ __launch_bounds__(THREADS, 1)
void mps_hmma_kernel(const float* __restrict__ first,
                     const float* __restrict__ last,
                     const float* __restrict__ w,
                     const float* __restrict__ bias,
                     float* __restrict__ out) {
    extern __shared__ __align__(1024) char smem[];
    const uint32_t sb = smem_u32(smem);
    const uint32_t mb = sb + SM_MB;
    float* fl    = (float*)(smem + SM_FL);
    float* cS    = fl;            // [2][64]
    float* sS    = fl + 128;      // [2][64]
    float* c2S   = fl + 256;      // [64] site 255
    float* s2S   = fl + 320;
    float* lastS = fl + 384;      // [256]
    float* red   = fl + 640;      // [512]

    const int tid  = threadIdx.x;
    const int lane = tid & 31;
    const int wd   = tid >> 5;
    const int gA   = lane >> 3;
    const int rowA = lane & 7;
    const int g4   = lane >> 2;
    const int q4   = lane & 3;
    const int b0   = blockIdx.x * BM;

    lastS[tid] = __ldg(&last[tid]);

    uint4 Bb0[4], Bb1[4];
#define LOADB(R, step_, c_) do {                                             \
    const uint4* _p = (const uint4*)(g_B + (size_t)(step_) * 65536)          \
                    + ((c_) * 8 + wd) * 128 + lane;                          \
    R[0] = __ldg(_p); R[1] = __ldg(_p + 32);                                 \
    R[2] = __ldg(_p + 64); R[3] = __ldg(_p + 96);                            \
} while (0)

    LOADB(Bb0, 0, wd);

    // ---- A0 full tile into buf 0 ----
    for (int i = tid; i < BM * D_; i += THREADS) {
        int r = i >> 7, k = i & 127;
        float c0 = __ldg(&g_cos[b0 + r]);
        float s0 = __ldg(&g_sin[b0 + r]);
        float v = __ldg(&first[k]) * c0 + __ldg(&first[D_ + k]) * s0;
        __nv_bfloat16 bh = __float2bfloat16(v);
        float fh = __bfloat162float(bh);
        __nv_bfloat16 bl = __float2bfloat16(v - fh);
        int el = ((r >> 3) * 16 + (k >> 3)) * 64 + (r & 7) * 8 + (k & 7);
        ((__nv_bfloat16*)smem)[el]        = bh;
        ((__nv_bfloat16*)smem)[8192 + el] = bl;
    }

    // ---- held local A-frags for step 0 (chunk wd) ----
    uint32_t aHloc[4][4], aLloc[4][4];
#pragma unroll
    for (int mt = 0; mt < 4; ++mt) {
        int r1 = mt * 16 + g4, r2 = r1 + 8;
        float c1 = __ldg(&g_cos[b0 + r1]), s1 = __ldg(&g_sin[b0 + r1]);
        float c2_ = __ldg(&g_cos[b0 + r2]), s2_ = __ldg(&g_sin[b0 + r2]);
#pragma unroll
        for (int n8 = 0; n8 < 2; ++n8) {
            int k0 = wd * 16 + n8 * 8 + 2 * q4;
            float f0 = __ldg(&first[k0]),     g0 = __ldg(&first[128 + k0]);
            float f1 = __ldg(&first[k0 + 1]), g1 = __ldg(&first[129 + k0]);
            split2(f0 * c1 + g0 * s1, f1 * c1 + g1 * s1,
                   aHloc[mt][n8 * 2], aLloc[mt][n8 * 2]);
            split2(f0 * c2_ + g0 * s2_, f1 * c2_ + g1 * s2_,
                   aHloc[mt][n8 * 2 + 1], aLloc[mt][n8 * 2 + 1]);
        }
    }

    // pre-stage phi site 1 into slot 1
    if (tid < BM) {
        cS[64 + tid] = __ldg(&g_cos[(size_t)B_ + b0 + tid]);
        sS[64 + tid] = __ldg(&g_sin[(size_t)B_ + b0 + tid]);
    }
    if (tid == 0) mbar_init(mb, THREADS);
    __syncthreads();
    mbar_arrive(mb);             // phase 0: prologue published

#define SWEEP(AF, MB_, CUR)                                                  \
    _Pragma("unroll") for (int mt = 0; mt < 4; ++mt)                         \
    _Pragma("unroll") for (int d2 = 0; d2 < 2; ++d2)                         \
    _Pragma("unroll") for (int n8 = 0; n8 < 2; ++n8) {                       \
        const int f = (MB_) + d2 * 2 + n8;                                   \
        mma16816(acc[mt][d2][n8], AF[mt],                                    \
                 (const uint32_t*)&CUR[f >> 1] + (f & 1) * 2);               \
    }

#define BODY(jv, CUR, NXT) {                                                 \
    const int c_ = (wd + (jv)) & 7;                                          \
    if ((jv) < 7)             LOADB(NXT, m, (wd + (jv) + 1) & 7);            \
    else if (m < NSTEP - 1)   LOADB(NXT, m + 1, wd);                         \
    uint32_t aH[4][4], aL[4][4];                                             \
    _Pragma("unroll") for (int mt = 0; mt < 4; ++mt) {                       \
        uint32_t off = (uint32_t)(((mt * 2 + (gA & 1)) * 16 +                \
                       (c_ * 2 + (gA >> 1))) * 128 + rowA * 16);             \
        ldsm4(aH[mt], sb + acur + off);                                      \
        ldsm4(aL[mt], sb + acur + 16384 + off);                              \
    }                                                                        \
    SWEEP(aH, 0, CUR)                                                        \
    SWEEP(aL, 0, CUR)                                                        \
    SWEEP(aH, 4, CUR)                                                        \
}

    // ---- site loop: split-phase barrier per step ----
#pragma unroll 1
    for (int m = 0; m < NSTEP; ++m) {
        const uint32_t acur = (uint32_t)((m & 1) * 32768);
        const uint32_t anxt = acur ^ 32768u;

        float acc[4][2][2][4];
#pragma unroll
        for (int mt = 0; mt < 4; ++mt)
#pragma unroll
            for (int d2 = 0; d2 < 2; ++d2)
#pragma unroll
                for (int n8 = 0; n8 < 2; ++n8)
#pragma unroll
                    for (int q = 0; q < 4; ++q) acc[mt][d2][n8][q] = 0.0f;

        // j = 0: local chunk from held registers (no barrier needed)
        LOADB(Bb1, m, (wd + 1) & 7);
        SWEEP(aHloc, 0, Bb0)
        SWEEP(aLloc, 0, Bb0)
        SWEEP(aHloc, 4, Bb0)

        // wait: all warps' previous-step epilogues published
        mbar_wait(mb, (uint32_t)(m & 1));

        // stage phi site m+2 into slot m&1 (safe post-wait)
        if (tid < BM) {
            cS[(m & 1) * 64 + tid] =
                __ldg(&g_cos[(size_t)(m + 2) * B_ + b0 + tid]);
            sS[(m & 1) * 64 + tid] =
                __ldg(&g_sin[(size_t)(m + 2) * B_ + b0 + tid]);
        }
        if (m == NSTEP - 2 && tid >= 64 && tid < 128) {
            int t = tid - 64;
            c2S[t] = __ldg(&g_cos[(size_t)(NSITE - 1) * B_ + b0 + t]);
            s2S[t] = __ldg(&g_sin[(size_t)(NSITE - 1) * B_ + b0 + t]);
        }

        BODY(1, Bb1, Bb0)
        BODY(2, Bb0, Bb1)
        BODY(3, Bb1, Bb0)
        BODY(4, Bb0, Bb1)
        BODY(5, Bb1, Bb0)
        BODY(6, Bb0, Bb1)

        const int slot = ((m + 1) & 1) * 64;
        if (m < NSTEP - 1) {
            // ---- j=7 FUSED with epilogue, per m-tile: 12 MMAs for tile mt,
            //      then mt's parity-combine + hi/lo split + stsm while
            //      mt+1's MMAs keep the tensor pipe busy. ----
            const int c7 = (wd + 7) & 7;
            LOADB(Bb0, m + 1, wd);   // next step's j=0 chunk
            uint32_t aH7[4][4], aL7[4][4];
#pragma unroll
            for (int mt = 0; mt < 4; ++mt) {
                uint32_t off = (uint32_t)(((mt * 2 + (gA & 1)) * 16 +
                               (c7 * 2 + (gA >> 1))) * 128 + rowA * 16);
                ldsm4(aH7[mt], sb + acur + off);
                ldsm4(aL7[mt], sb + acur + 16384 + off);
            }
#pragma unroll
            for (int mt = 0; mt < 4; ++mt) {
                // 12 MMAs of tile mt (products on both parities, both n8)
#pragma unroll
                for (int d2 = 0; d2 < 2; ++d2)
#pragma unroll
                    for (int n8 = 0; n8 < 2; ++n8) {
                        const int fh_ = d2 * 2 + n8;
                        const int fl_ = 4 + d2 * 2 + n8;
                        const uint32_t* bh =
                            (const uint32_t*)&Bb1[fh_ >> 1] + (fh_ & 1) * 2;
                        const uint32_t* bl =
                            (const uint32_t*)&Bb1[fl_ >> 1] + (fl_ & 1) * 2;
                        mma16816(acc[mt][d2][n8], aH7[mt], bh);
                        mma16816(acc[mt][d2][n8], aL7[mt], bh);
                        mma16816(acc[mt][d2][n8], aH7[mt], bl);
                    }
                // epilogue of tile mt (overlaps tile mt+1's MMAs)
                int rb = mt * 16 + g4;
                float cl = cS[slot + rb], ch = cS[slot + rb + 8];
                float sl = sS[slot + rb], sh = sS[slot + rb + 8];
#pragma unroll
                for (int n8 = 0; n8 < 2; ++n8) {
                    float* E = acc[mt][0][n8];
                    float* O = acc[mt][1][n8];
                    split2(cl * E[0] + sl * O[0], cl * E[1] + sl * O[1],
                           aHloc[mt][n8 * 2], aLloc[mt][n8 * 2]);
                    split2(ch * E[2] + sh * O[2], ch * E[3] + sh * O[3],
                           aHloc[mt][n8 * 2 + 1], aLloc[mt][n8 * 2 + 1]);
                }
                uint32_t off = (uint32_t)(((mt * 2 + (gA & 1)) * 16 +
                               (wd * 2 + (gA >> 1))) * 128 + rowA * 16);
                stsm4(sb + anxt + off, aHloc[mt][0], aHloc[mt][1],
                      aHloc[mt][2], aHloc[mt][3]);
                stsm4(sb + anxt + 16384 + off, aLloc[mt][0], aLloc[mt][1],
                      aLloc[mt][2], aLloc[mt][3]);
            }
            mbar_arrive(mb);
        } else {
            BODY(7, Bb1, Bb0)
            // ---- final: contract with last site + linear head ----
            float part[4][2];
#pragma unroll
            for (int mt = 0; mt < 4; ++mt) { part[mt][0] = 0.f; part[mt][1] = 0.f; }
#pragma unroll
            for (int mt = 0; mt < 4; ++mt) {
                int rb = mt * 16 + g4;
                float cl = cS[slot + rb], ch = cS[slot + rb + 8];
                float sl = sS[slot + rb], sh = sS[slot + rb + 8];
                float c2l = c2S[rb], c2h = c2S[rb + 8];
                float s2l = s2S[rb], s2h = s2S[rb + 8];
#pragma unroll
                for (int n8 = 0; n8 < 2; ++n8) {
                    float* E = acc[mt][0][n8];
                    float* O = acc[mt][1][n8];
                    int n0 = wd * 16 + n8 * 8 + 2 * q4;
                    float w0l = lastS[2 * n0] * c2l + lastS[2 * n0 + 1] * s2l;
                    float w1l = lastS[2 * n0 + 2] * c2l + lastS[2 * n0 + 3] * s2l;
                    float w0h = lastS[2 * n0] * c2h + lastS[2 * n0 + 1] * s2h;
                    float w1h = lastS[2 * n0 + 2] * c2h + lastS[2 * n0 + 3] * s2h;
                    part[mt][0] += (cl * E[0] + sl * O[0]) * w0l
                                 + (cl * E[1] + sl * O[1]) * w1l;
                    part[mt][1] += (ch * E[2] + sh * O[2]) * w0h
                                 + (ch * E[3] + sh * O[3]) * w1h;
                }
            }
#pragma unroll
            for (int o = 1; o <= 2; o <<= 1)
#pragma unroll
                for (int mt = 0; mt < 4; ++mt) {
                    part[mt][0] += __shfl_xor_sync(0xffffffffu, part[mt][0], o);
                    part[mt][1] += __shfl_xor_sync(0xffffffffu, part[mt][1], o);
                }
            if (q4 == 0) {
#pragma unroll
                for (int mt = 0; mt < 4; ++mt) {
                    red[wd * 64 + mt * 16 + g4]     = part[mt][0];
                    red[wd * 64 + mt * 16 + g4 + 8] = part[mt][1];
                }
            }
            __syncthreads();
            if (tid < BM) {
                float tot = 0.f;
#pragma unroll
                for (int ww = 0; ww < 8; ++ww) tot += red[ww * 64 + tid];
#pragma unroll
                for (int o = 0; o < OUT_; ++o)
                    out[(size_t)(b0 + tid) * OUT_ + o] =
                        tot * __ldg(&w[o]) + __ldg(&bias[o]);
            }
        }
    }
#undef BODY
#undef SWEEP
#undef LOADB
}

// ============================================================================
// Launch: 2 kernels.
// ============================================================================
extern "C" void kernel_launch(void* const* d_in, const int* in_sizes, int n_in,
                              void* d_out, int out_size) {
    const float* x     = (const float*)d_in[0];  // [B, N]
    const float* first = (const float*)d_in[1];  // [1, 2, D]
    const float* mid   = (const float*)d_in[2];  // [N-2, D, 2, D]
    const float* last  = (const float*)d_in[3];  // [D, 2, 1]
    const float* w     = (const float*)d_in[4];  // [OUT, 1]
    const float* bias  = (const float*)d_in[5];  // [OUT]
    float* out = (float*)d_out;                  // [B, OUT]

    cudaFuncSetAttribute(mps_hmma_kernel,
                         cudaFuncAttributeMaxDynamicSharedMemorySize,
                         SMEM_TOTAL);

    prep_kernel<<<1024 + (NSTEP * 8192 + PREP_T - 1) / PREP_T, PREP_T>>>(x, mid);
    mps_hmma_kernel<<<NCTA, THREADS, SMEM_TOTAL>>>(first, last, w, bias, out);
}